// round 11
// baseline (speedup 1.0000x reference)
#include <cuda_runtime.h>
#include <math.h>

// ---------------------------------------------------------------------------
// RandomProjection: out[b,o] = mean_s( cos(x[b,s,:], p[o,:]) )
// SINGLE fused kernel:
//   Phase A: blocks 0..255 reduce x -> g_part[8][32][768];
//            blocks 256..511 p-norms -> g_rpn, zero(out)
//   Grid barrier (monotonic ticket, all 512 blocks resident by construction)
//   Phase B: all blocks: transposed-smem register-tiled GEMM,
//            partial-combine folded into staging, red.add.v4 epilogue
// ---------------------------------------------------------------------------

#define B_    32
#define S_    512
#define D_    768
#define O_    2048
#define EPS_  1e-8f

#define GRID   512
#define KSPLIT 32
#define KB     24            // k floats per gemm block
#define OTILE  128           // o rows per gemm block
#define PMB    36            // msm pitch [k][b]
#define PPO    132           // psm pitch [k][o]

__device__ float    g_part[8 * B_ * D_];  // [e][b][d] race-free partials
__device__ float    g_rpn[O_];            // 1/max(||p_o||,eps)
__device__ unsigned g_bar;                // monotonic barrier counter (never reset)

__global__ void __launch_bounds__(256, 4)
fused_kernel(const float* __restrict__ x, const float* __restrict__ p,
             float* __restrict__ out) {
    __shared__ float sh[6144];   // 24 KB: phase A tree / phase B msm+psm

    const int tid  = threadIdx.x;
    const int warp = tid >> 5;
    const int lane = tid & 31;
    const int blk  = blockIdx.x;

    // ================= Phase A =================
    if (blk < 256) {
        // x reduce: b = blk>>3, eighth e = blk&7 -> 64 s-rows, 8 per warp
        const int b = blk >> 3;
        const int e = blk & 7;
        const float4* base = reinterpret_cast<const float4*>(
            x + ((size_t)b * S_ + (size_t)e * 64 + (size_t)warp * 8) * D_);
        const float inv_S = 1.0f / (float)S_;

        float4 acc[6];
        #pragma unroll
        for (int c = 0; c < 6; c++) acc[c] = make_float4(0.f, 0.f, 0.f, 0.f);

        #pragma unroll
        for (int r = 0; r < 8; r++) {
            float4 v[6];
            #pragma unroll
            for (int c = 0; c < 6; c++) v[c] = base[r * 192 + lane + 32 * c];

            float ss = 0.f;
            #pragma unroll
            for (int c = 0; c < 6; c++)
                ss += v[c].x * v[c].x + v[c].y * v[c].y
                    + v[c].z * v[c].z + v[c].w * v[c].w;
            #pragma unroll
            for (int off = 16; off > 0; off >>= 1)
                ss += __shfl_xor_sync(0xFFFFFFFFu, ss, off);

            const float scale = inv_S / fmaxf(sqrtf(ss), EPS_);
            #pragma unroll
            for (int c = 0; c < 6; c++) {
                acc[c].x += v[c].x * scale;
                acc[c].y += v[c].y * scale;
                acc[c].z += v[c].z * scale;
                acc[c].w += v[c].w * scale;
            }
        }

        float4* sm4 = reinterpret_cast<float4*>(sh);
        #pragma unroll
        for (int c = 0; c < 6; c++)
            sm4[warp * 192 + lane + 32 * c] = acc[c];
        __syncthreads();

        if (tid < 192) {
            float4 s = sm4[tid];
            #pragma unroll
            for (int w = 1; w < 8; w++) {
                const float4 t = sm4[w * 192 + tid];
                s.x += t.x; s.y += t.y; s.z += t.z; s.w += t.w;
            }
            reinterpret_cast<float4*>(g_part)[(e * B_ + b) * 192 + tid] = s;
        }
    } else {
        // p-norms (8 rows/block, one per warp) + zero out-slice
        const int j = blk - 256;               // 0..255
        if (tid < 64)
            reinterpret_cast<float4*>(out)[j * 64 + tid] =
                make_float4(0.f, 0.f, 0.f, 0.f);

        const int o = j * 8 + warp;
        const float4* prow = reinterpret_cast<const float4*>(p + (size_t)o * D_);
        float ss = 0.f;
        #pragma unroll
        for (int c = 0; c < 6; c++) {
            const float4 v = prow[lane + 32 * c];
            ss += v.x * v.x + v.y * v.y + v.z * v.z + v.w * v.w;
        }
        #pragma unroll
        for (int off = 16; off > 0; off >>= 1)
            ss += __shfl_xor_sync(0xFFFFFFFFu, ss, off);
        if (lane == 0) g_rpn[o] = 1.0f / fmaxf(sqrtf(ss), EPS_);
    }

    // ================= Grid barrier (monotonic ticket) =================
    if (tid == 0) {
        __threadfence();                       // release phase-A writes
        const unsigned my = atomicAdd(&g_bar, 1u) + 1u;
        const unsigned target = (my + (GRID - 1u)) & ~(unsigned)(GRID - 1u);
        unsigned cur;
        while (true) {
            asm volatile("ld.acquire.gpu.global.u32 %0, [%1];"
                         : "=r"(cur) : "l"(&g_bar));
            if ((int)(cur - target) >= 0) break;
            __nanosleep(64);
        }
    }
    __syncthreads();

    // ================= Phase B: GEMM =================
    const int ot = blk >> 5;                   // 0..15
    const int kq = blk & 31;                   // 0..31
    const int k0 = kq * KB;

    float* msm = sh;                           // [KB][PMB]  = 864 floats
    float* psm = sh + 896;                     // [KB][PPO]  = 3168 floats

    // stage msm: combine 8 partials, transpose to [k][b]
    if (tid < 192) {
        const int b  = tid / 6;                // 0..31
        const int kc = tid - b * 6;            // float4 index 0..5
        const float4* gp = reinterpret_cast<const float4*>(g_part);
        const int col = (k0 >> 2) + kc;
        float4 s = gp[(0 * B_ + b) * 192 + col];
        #pragma unroll
        for (int e = 1; e < 8; e++) {
            const float4 t = gp[(e * B_ + b) * 192 + col];
            s.x += t.x; s.y += t.y; s.z += t.z; s.w += t.w;
        }
        msm[(kc * 4 + 0) * PMB + b] = s.x;
        msm[(kc * 4 + 1) * PMB + b] = s.y;
        msm[(kc * 4 + 2) * PMB + b] = s.z;
        msm[(kc * 4 + 3) * PMB + b] = s.w;
    }
    // stage psm: p * rpn, transpose to [k][o]
    #pragma unroll
    for (int t2 = 0; t2 < 3; t2++) {
        const int i  = tid + t2 * 256;         // 0..767
        const int o  = i / 6;                  // 0..127
        const int kc = i - o * 6;              // 0..5
        const float4 v = *reinterpret_cast<const float4*>(
            p + (size_t)(ot * OTILE + o) * D_ + k0 + kc * 4);
        const float rp = g_rpn[ot * OTILE + o];
        psm[(kc * 4 + 0) * PPO + o] = v.x * rp;
        psm[(kc * 4 + 1) * PPO + o] = v.y * rp;
        psm[(kc * 4 + 2) * PPO + o] = v.z * rp;
        psm[(kc * 4 + 3) * PPO + o] = v.w * rp;
    }
    __syncthreads();

    const int wb = warp >> 2;                  // 0..1
    const int wo = warp & 3;                   // 0..3
    const int bi = lane >> 3;                  // 0..3
    const int oj = lane & 7;                   // 0..7

    const float* mb = &msm[wb * 16 + bi * 4];
    const float* pb = &psm[wo * 32 + oj * 4];

    float acc[4][4];
    #pragma unroll
    for (int rr = 0; rr < 4; rr++)
        #pragma unroll
        for (int ss = 0; ss < 4; ss++) acc[rr][ss] = 0.f;

    #pragma unroll 8
    for (int k = 0; k < KB; k++) {
        const float4 mv = *reinterpret_cast<const float4*>(mb + k * PMB);
        const float4 pv = *reinterpret_cast<const float4*>(pb + k * PPO);
        acc[0][0] += mv.x * pv.x;  acc[0][1] += mv.x * pv.y;
        acc[0][2] += mv.x * pv.z;  acc[0][3] += mv.x * pv.w;
        acc[1][0] += mv.y * pv.x;  acc[1][1] += mv.y * pv.y;
        acc[1][2] += mv.y * pv.z;  acc[1][3] += mv.y * pv.w;
        acc[2][0] += mv.z * pv.x;  acc[2][1] += mv.z * pv.y;
        acc[2][2] += mv.z * pv.z;  acc[2][3] += mv.z * pv.w;
        acc[3][0] += mv.w * pv.x;  acc[3][1] += mv.w * pv.y;
        acc[3][2] += mv.w * pv.z;  acc[3][3] += mv.w * pv.w;
    }

    const int o0 = ot * OTILE + wo * 32 + oj * 4;
    #pragma unroll
    for (int rr = 0; rr < 4; rr++) {
        float* dst = out + (size_t)(wb * 16 + bi * 4 + rr) * O_ + o0;
        asm volatile("red.global.add.v4.f32 [%0], {%1, %2, %3, %4};"
                     :: "l"(dst), "f"(acc[rr][0]), "f"(acc[rr][1]),
                        "f"(acc[rr][2]), "f"(acc[rr][3])
                     : "memory");
    }
}

// ---------------------------------------------------------------------------
extern "C" void kernel_launch(void* const* d_in, const int* in_sizes, int n_in,
                              void* d_out, int out_size) {
    const float* x = (const float*)d_in[0];   // [32, 512, 768]
    const float* p = (const float*)d_in[1];   // [2048, 768]
    float*     out = (float*)d_out;           // [32, 2048]

    (void)in_sizes; (void)n_in; (void)out_size;

    fused_kernel<<<GRID, 256>>>(x, p, out);
}